// round 15
// baseline (speedup 1.0000x reference)
#include <cuda_runtime.h>
#include <cuda_fp16.h>
#include <cstdint>
#include <cstddef>

// ---------------- problem constants (fixed by the dataset) ----------------
#define Bn     16
#define SEQn   256
#define DIMn   1024
#define HEADSn 16
#define DHEADn 64
#define INNERn 1024
#define Mmem   8
#define TXTn   77
#define KVn    (Mmem*SEQn + TXTn)   // 2125
#define KVP    2176                 // padded kv for transposed V
#define MSn    (Mmem*SEQn)          // 2048
#define SCALEf 0.125f               // 64^-0.5

#define ROWS_X   (Bn*SEQn)          // 4096
#define ROWS_C   (Bn*KVn)           // 34000
#define BHn      (Bn*HEADSn)        // 256

// ---------------- scratch (device globals: no allocation allowed) ---------
__device__ __half g_Qh[ROWS_X * INNERn];        // rotated+scaled Q (half)
__device__ __half g_Kh[ROWS_C * INNERn];        // biased+rotated K (half)
__device__ __half g_Vt[(size_t)BHn * 64 * KVP]; // V transposed per (b,h): [d][kv]
__device__ __half g_Oh[ROWS_X * INNERn];        // attention output (half)
__device__ __half g_Whkv[2 * DIMn * INNERn];    // [Wtk;Wtv] K-major halves
__device__ __half g_Whq[DIMn * INNERn];         // Wq K-major half
__device__ __half g_Who[DIMn * INNERn];         // Wo K-major half
__device__ __half g_Ch[ROWS_C * DIMn];          // half(cond)
__device__ __half g_Xh[ROWS_X * DIMn];          // half(x)
__device__ float  g_cosf[64*64*64];
__device__ float  g_sinf[64*64*64];

// ---------------- helpers --------------------------------------------------
__device__ __forceinline__ uint32_t smem_u32(const void* p) {
    uint32_t a;
    asm("{ .reg .u64 t; cvta.to.shared.u64 t, %1; cvt.u32.u64 %0, t; }" : "=r"(a) : "l"(p));
    return a;
}
__device__ __forceinline__ void rot_pair(float2& v, float bias,
                                         const float* __restrict__ cf,
                                         const float* __restrict__ sf, int fo) {
    const float t0 = v.x + bias, t1 = v.y + bias;
    v.x = t0 * cf[fo]     - t1 * sf[fo];
    v.y = t1 * cf[fo + 1] + t0 * sf[fo + 1];
}
#define MMA_F16(d0,d1,d2,d3,a0,a1,a2,a3,b0,b1)                                \
    asm volatile(                                                             \
        "mma.sync.aligned.m16n8k16.row.col.f32.f16.f16.f32 "                  \
        "{%0,%1,%2,%3},{%4,%5,%6,%7},{%8,%9},{%0,%1,%2,%3};"                  \
        : "+f"(d0), "+f"(d1), "+f"(d2), "+f"(d3)                              \
        : "r"(a0), "r"(a1), "r"(a2), "r"(a3), "r"(b0), "r"(b1))
#define CP16(dst, src)     asm volatile("cp.async.cg.shared.global [%0], [%1], 16;" :: "r"(dst), "l"(src))
#define CP16P(dst, src, p) asm volatile("cp.async.cg.shared.global [%0], [%1], 16, %2;" :: "r"(dst), "l"(src), "r"(p))
#define CP_COMMIT()        asm volatile("cp.async.commit_group;" ::: "memory")
#define CP_WAIT(n)         asm volatile("cp.async.wait_group %0;" :: "n"(n) : "memory")

#define HSTR 40   // smem row stride in halves (80B): conflict-free fragments

// ====== fp16 GEMM core loop (shared by all projection kernels) =============
// Computes d[4][8][4] (+=) for a 128x128 tile over K=1024, BK=32, dbl-buffer.
#define F16_GEMM_BODY(Aptr, Bptr, Mv)                                          \
    auto issue = [&](int buf, int kt) {                                        \
        const int k0 = kt * 32;                                                \
        _Pragma("unroll")                                                      \
        for (int e = 0; e < 4; e++) {                                          \
            int idx = tid + e * 128;                                           \
            int row = idx >> 2, c8 = (idx & 3) * 8;                            \
            int ga = m0 + row;                                                 \
            int pa = (ga < Mv) ? 16 : 0;                                       \
            if (ga >= Mv) ga = Mv - 1;                                         \
            uint32_t da = smem_u32(&As[buf][row * HSTR + c8]);                 \
            CP16P(da, Aptr + (size_t)ga * 1024u + k0 + c8, pa);                \
            uint32_t db = smem_u32(&Bs[buf][row * HSTR + c8]);                 \
            CP16(db, Bptr + (size_t)(n0 + row) * 1024u + k0 + c8);             \
        }                                                                      \
        CP_COMMIT();                                                           \
    };                                                                         \
    issue(0, 0);                                                               \
    issue(1, 1);                                                               \
    for (int kt = 0; kt < 32; kt++) {                                          \
        const int buf = kt & 1;                                                \
        if (kt < 31) CP_WAIT(1);                                               \
        else         CP_WAIT(0);                                               \
        __syncthreads();                                                       \
        _Pragma("unroll")                                                      \
        for (int ks = 0; ks < 2; ks++) {                                       \
            uint32_t af[4][4], bf[8][2];                                       \
            _Pragma("unroll")                                                  \
            for (int i = 0; i < 4; i++) {                                      \
                const __half* base = &As[buf][(wm + i * 16) * HSTR + ks * 16]; \
                af[i][0] = *(const uint32_t*)&base[(g)     * HSTR + 2 * tg];   \
                af[i][1] = *(const uint32_t*)&base[(g + 8) * HSTR + 2 * tg];   \
                af[i][2] = *(const uint32_t*)&base[(g)     * HSTR + 2 * tg + 8];\
                af[i][3] = *(const uint32_t*)&base[(g + 8) * HSTR + 2 * tg + 8];\
            }                                                                  \
            _Pragma("unroll")                                                  \
            for (int j = 0; j < 8; j++) {                                      \
                const __half* base = &Bs[buf][(wn + j * 8 + g) * HSTR + ks * 16];\
                bf[j][0] = *(const uint32_t*)&base[2 * tg];                    \
                bf[j][1] = *(const uint32_t*)&base[2 * tg + 8];                \
            }                                                                  \
            _Pragma("unroll")                                                  \
            for (int i = 0; i < 4; i++)                                        \
                _Pragma("unroll")                                              \
                for (int j = 0; j < 8; j++)                                    \
                    MMA_F16(d[i][j][0], d[i][j][1], d[i][j][2], d[i][j][3],    \
                            af[i][0], af[i][1], af[i][2], af[i][3],            \
                            bf[j][0], bf[j][1]);                               \
        }                                                                      \
        __syncthreads();                                                       \
        if (kt + 2 < 32) issue(buf, kt + 2);                                   \
    }

// =================== fp16 GEMM: merged K|V projection ======================
__global__ __launch_bounds__(128, 2)
void gemm_kv_f16(const __half* __restrict__ A, const __half* __restrict__ Bt,
                 __half* __restrict__ Kh, __half* __restrict__ Vt,
                 const float* __restrict__ cf, const float* __restrict__ sf,
                 const float* __restrict__ rel_table,
                 const int* __restrict__ memidx, const int* __restrict__ cur,
                 int M)
{
    __shared__ __half As[2][128 * HSTR];
    __shared__ __half Bs[2][128 * HSTR];

    const int tid  = threadIdx.x;
    const int wid  = tid >> 5, lane = tid & 31;
    const int g    = lane >> 2, tg = lane & 3;
    const int wm   = (wid >> 1) * 64;
    const int wn   = (wid & 1) * 64;
    const int m0   = blockIdx.y * 128, n0 = blockIdx.x * 128;

    float d[4][8][4];
#pragma unroll
    for (int i = 0; i < 4; i++)
#pragma unroll
        for (int j = 0; j < 8; j++)
#pragma unroll
            for (int q = 0; q < 4; q++) d[i][j][q] = 0.f;

    F16_GEMM_BODY(A, Bt, M)

    // ---------------- epilogue ---------------------------------------------
    const bool kblk = (n0 < 1024);
    const int cb = kblk ? n0 : (n0 - 1024);

    const int cp = cur[0];
    const int ci = cp % 16;
    const int rs = ci % 4, cs = ci / 4, ts = cp / 16;
    const int hwarp = (n0 + wn) >> 6;

#pragma unroll
    for (int i = 0; i < 4; i++) {
        const int rA = m0 + wm + i * 16 + g;
        const int rB = rA + 8;

        float biasA = 0.f, biasB = 0.f;
        int fobA = 0, fobB = 0;
        bool tA = false, tB = false;
        if (kblk) {
            {
                const int b_ = rA / KVn, j = rA - b_ * KVn;
                if (j < MSn) {
                    const int m = j >> 8, jj = j & 255;
                    const int mi = memidx[m], mn = mi % 16;
                    const int rt = mn % 4, ct = mn / 4, tt = mi / 16;
                    const int rel = (rt - rs + 4) * 9 + (ct - cs + 4) + (tt - ts + 4) * 81;
                    biasA = rel_table[rel * HEADSn + hwarp];
                    fobA = (((rt * 16 + (jj >> 4)) << 6) + (ct * 16 + (jj & 15))) * 64;
                    tA = true;
                }
            }
            {
                const int b_ = rB / KVn, j = rB - b_ * KVn;
                if (j < MSn) {
                    const int m = j >> 8, jj = j & 255;
                    const int mi = memidx[m], mn = mi % 16;
                    const int rt = mn % 4, ct = mn / 4, tt = mi / 16;
                    const int rel = (rt - rs + 4) * 9 + (ct - cs + 4) + (tt - ts + 4) * 81;
                    biasB = rel_table[rel * HEADSn + hwarp];
                    fobB = (((rt * 16 + (jj >> 4)) << 6) + (ct * 16 + (jj & 15))) * 64;
                    tB = true;
                }
            }
        }

#pragma unroll
        for (int j = 0; j < 8; j++) {
            const int c  = cb + wn + j * 8 + tg * 2;
            const int d0 = (wn + j * 8 + tg * 2) & 63;
            float2 v0 = make_float2(d[i][j][0], d[i][j][1]);
            float2 v1 = make_float2(d[i][j][2], d[i][j][3]);
            if (kblk) {
                if (tA) rot_pair(v0, biasA, cf, sf, fobA + d0);
                if (tB) rot_pair(v1, biasB, cf, sf, fobB + d0);
                if (rA < M) *(__half2*)&Kh[(size_t)rA * 1024u + c] = __floats2half2_rn(v0.x, v0.y);
                if (rB < M) *(__half2*)&Kh[(size_t)rB * 1024u + c] = __floats2half2_rn(v1.x, v1.y);
            } else {
                const int hh = c >> 6, dd = c & 63;
                if (rA < M) {
                    const int b_ = rA / KVn, jv = rA - b_ * KVn;
                    __half* vt = Vt + ((size_t)(b_ * HEADSn + hh) * 64) * KVP + jv;
                    vt[(size_t)dd * KVP]       = __float2half_rn(v0.x);
                    vt[(size_t)(dd + 1) * KVP] = __float2half_rn(v0.y);
                }
                if (rB < M) {
                    const int b_ = rB / KVn, jv = rB - b_ * KVn;
                    __half* vt = Vt + ((size_t)(b_ * HEADSn + hh) * 64) * KVP + jv;
                    vt[(size_t)dd * KVP]       = __float2half_rn(v1.x);
                    vt[(size_t)(dd + 1) * KVP] = __float2half_rn(v1.y);
                }
            }
        }
    }
}

// =================== fp16 GEMM: Q projection (rotary+scale -> half) ========
__global__ __launch_bounds__(128, 2)
void gemm_q_f16(const __half* __restrict__ A, const __half* __restrict__ Bt,
                __half* __restrict__ Qh,
                const float* __restrict__ cf, const float* __restrict__ sf,
                const int* __restrict__ cur, int M)
{
    __shared__ __half As[2][128 * HSTR];
    __shared__ __half Bs[2][128 * HSTR];

    const int tid  = threadIdx.x;
    const int wid  = tid >> 5, lane = tid & 31;
    const int g    = lane >> 2, tg = lane & 3;
    const int wm   = (wid >> 1) * 64;
    const int wn   = (wid & 1) * 64;
    const int m0   = blockIdx.y * 128, n0 = blockIdx.x * 128;

    float d[4][8][4];
#pragma unroll
    for (int i = 0; i < 4; i++)
#pragma unroll
        for (int j = 0; j < 8; j++)
#pragma unroll
            for (int q = 0; q < 4; q++) d[i][j][q] = 0.f;

    F16_GEMM_BODY(A, Bt, M)

    const int ci = cur[0] % 16;
    const int rs = ci % 4, cs = ci / 4;

#pragma unroll
    for (int i = 0; i < 4; i++) {
        const int rA = m0 + wm + i * 16 + g;
        const int rB = rA + 8;
        int fobA, fobB;
        { const int s = rA & 255;
          fobA = (((rs * 16 + (s >> 4)) << 6) + (cs * 16 + (s & 15))) * 64; }
        { const int s = rB & 255;
          fobB = (((rs * 16 + (s >> 4)) << 6) + (cs * 16 + (s & 15))) * 64; }
#pragma unroll
        for (int j = 0; j < 8; j++) {
            const int c  = n0 + wn + j * 8 + tg * 2;
            const int d0 = (wn + j * 8 + tg * 2) & 63;
            float2 v0 = make_float2(d[i][j][0], d[i][j][1]);
            float2 v1 = make_float2(d[i][j][2], d[i][j][3]);
            rot_pair(v0, 0.f, cf, sf, fobA + d0);
            rot_pair(v1, 0.f, cf, sf, fobB + d0);
            if (rA < M) *(__half2*)&Qh[(size_t)rA * 1024u + c] =
                __floats2half2_rn(v0.x * SCALEf, v0.y * SCALEf);
            if (rB < M) *(__half2*)&Qh[(size_t)rB * 1024u + c] =
                __floats2half2_rn(v1.x * SCALEf, v1.y * SCALEf);
        }
    }
}

// =================== fp16 GEMM: out projection (bias -> fp32) ==============
__global__ __launch_bounds__(128, 2)
void gemm_o_f16(const __half* __restrict__ A, const __half* __restrict__ Bt,
                float* __restrict__ C, const float* __restrict__ bias, int M)
{
    __shared__ __half As[2][128 * HSTR];
    __shared__ __half Bs[2][128 * HSTR];

    const int tid  = threadIdx.x;
    const int wid  = tid >> 5, lane = tid & 31;
    const int g    = lane >> 2, tg = lane & 3;
    const int wm   = (wid >> 1) * 64;
    const int wn   = (wid & 1) * 64;
    const int m0   = blockIdx.y * 128, n0 = blockIdx.x * 128;

    float d[4][8][4];
#pragma unroll
    for (int i = 0; i < 4; i++)
#pragma unroll
        for (int j = 0; j < 8; j++)
#pragma unroll
            for (int q = 0; q < 4; q++) d[i][j][q] = 0.f;

    F16_GEMM_BODY(A, Bt, M)

#pragma unroll
    for (int i = 0; i < 4; i++) {
        const int rA = m0 + wm + i * 16 + g;
        const int rB = rA + 8;
#pragma unroll
        for (int j = 0; j < 8; j++) {
            const int c = n0 + wn + j * 8 + tg * 2;
            const float b0 = bias[c], b1 = bias[c + 1];
            float2 v0 = make_float2(d[i][j][0] + b0, d[i][j][1] + b1);
            float2 v1 = make_float2(d[i][j][2] + b0, d[i][j][3] + b1);
            if (rA < M) *(float2*)&C[(size_t)rA * 1024u + c] = v0;
            if (rB < M) *(float2*)&C[(size_t)rB * 1024u + c] = v1;
        }
    }
}

// =================== fused flash attention (fp16 mma) ======================
#define QH_O 0                         // 128 x 72 halves
#define KH_O (QH_O + 128*72*2)         // 64 x 72 halves
#define VT_O (KH_O + 64*72*2)          // 64 x 72 halves (rows = d)
#define PH_O (VT_O + 64*72*2)          // 128 x 72 halves
#define SS_O (PH_O + 128*72*2)         // 128 x 68 floats
#define MR_O (SS_O + 128*68*4)
#define LR_O (MR_O + 128*4)
#define AR_O (LR_O + 128*4)
#define FL_SMEM (AR_O + 128*4)         // 91648 bytes

#define NCHUNK ((KVn + 63) / 64)       // 34

__global__ __launch_bounds__(256, 2)
void flash_attn(const __half* __restrict__ Q, const __half* __restrict__ K,
                const __half* __restrict__ Vt, __half* __restrict__ O)
{
    extern __shared__ char smc[];
    __half* QH = (__half*)(smc + QH_O);
    __half* KH = (__half*)(smc + KH_O);
    __half* VT = (__half*)(smc + VT_O);
    __half* PH = (__half*)(smc + PH_O);
    float*  SS = (float*)(smc + SS_O);
    float*  MR = (float*)(smc + MR_O);
    float*  LR = (float*)(smc + LR_O);
    float*  AR = (float*)(smc + AR_O);

    const int tid = threadIdx.x;
    const int wid = tid >> 5, lane = tid & 31;
    const int g = lane >> 2, tg = lane & 3;
    const int bh = blockIdx.y, b = bh >> 4, h = bh & 15;
    const int m0 = blockIdx.x * 128;

    const __half* Qb = Q + ((size_t)(b * SEQn + m0)) * 1024u + h * 64;
    const __half* Kb = K + ((size_t)b * KVn) * 1024u + h * 64;
    const __half* Vb = Vt + ((size_t)bh * 64) * KVP;

#pragma unroll
    for (int e = 0; e < 4; e++) {
        int idx = tid + e * 256;
        int r = idx >> 3, c8 = (idx & 7) * 8;
        uint32_t dq = smem_u32(&QH[r * 72 + c8]);
        CP16(dq, Qb + (size_t)r * 1024u + c8);
    }
    CP_COMMIT();
    if (tid < 128) { MR[tid] = -1e30f; LR[tid] = 0.f; }

    float oacc[4][2][4];
#pragma unroll
    for (int i = 0; i < 4; i++)
#pragma unroll
        for (int j = 0; j < 2; j++)
#pragma unroll
            for (int q = 0; q < 4; q++) oacc[i][j][q] = 0.f;

    const int om = (wid >> 2) * 64;
    const int on = (wid & 3) * 16;

    for (int t = 0; t < NCHUNK; t++) {
        const int kv0 = t * 64;
        const int rows = (KVn - kv0 < 64) ? (KVn - kv0) : 64;

#pragma unroll
        for (int e = 0; e < 4; e++) {
            int idx = tid + e * 256;
            int r = (idx >> 3) & 63, c8 = (idx & 7) * 8;
            if (idx < 512) {
                int kvr = kv0 + r; if (kvr >= KVn) kvr = KVn - 1;
                uint32_t dk = smem_u32(&KH[r * 72 + c8]);
                CP16(dk, Kb + (size_t)kvr * 1024u + c8);
            } else {
                uint32_t dv = smem_u32(&VT[r * 72 + c8]);
                CP16(dv, Vb + (size_t)r * KVP + kv0 + c8);
            }
        }
        CP_COMMIT();
        CP_WAIT(0);
        __syncthreads();

        float s[4][2][4];
#pragma unroll
        for (int i = 0; i < 4; i++)
#pragma unroll
            for (int j = 0; j < 2; j++)
#pragma unroll
                for (int q = 0; q < 4; q++) s[i][j][q] = 0.f;

#pragma unroll
        for (int ks = 0; ks < 4; ks++) {
            uint32_t af[4][4], bf[2][2];
#pragma unroll
            for (int i = 0; i < 4; i++) {
                const __half* base = &QH[(om + i * 16) * 72 + ks * 16];
                af[i][0] = *(const uint32_t*)&base[(g)     * 72 + 2 * tg];
                af[i][1] = *(const uint32_t*)&base[(g + 8) * 72 + 2 * tg];
                af[i][2] = *(const uint32_t*)&base[(g)     * 72 + 2 * tg + 8];
                af[i][3] = *(const uint32_t*)&base[(g + 8) * 72 + 2 * tg + 8];
            }
#pragma unroll
            for (int j = 0; j < 2; j++) {
                const __half* base = &KH[(on + j * 8 + g) * 72 + ks * 16];
                bf[j][0] = *(const uint32_t*)&base[2 * tg];
                bf[j][1] = *(const uint32_t*)&base[2 * tg + 8];
            }
#pragma unroll
            for (int i = 0; i < 4; i++)
#pragma unroll
                for (int j = 0; j < 2; j++)
                    MMA_F16(s[i][j][0], s[i][j][1], s[i][j][2], s[i][j][3],
                            af[i][0], af[i][1], af[i][2], af[i][3],
                            bf[j][0], bf[j][1]);
        }
#pragma unroll
        for (int i = 0; i < 4; i++) {
            const int r0 = om + i * 16 + g;
#pragma unroll
            for (int j = 0; j < 2; j++) {
                const int c = on + j * 8 + tg * 2;
                SS[r0 * 68 + c]           = s[i][j][0];
                SS[r0 * 68 + c + 1]       = s[i][j][1];
                SS[(r0 + 8) * 68 + c]     = s[i][j][2];
                SS[(r0 + 8) * 68 + c + 1] = s[i][j][3];
            }
        }
        __syncthreads();

#pragma unroll 4
        for (int rr = 0; rr < 16; rr++) {
            const int r = wid * 16 + rr;
            const int c0 = lane * 2;
            float v0 = (c0     < rows) ? SS[r * 68 + c0]     : -1e30f;
            float v1 = (c0 + 1 < rows) ? SS[r * 68 + c0 + 1] : -1e30f;
            float mx = fmaxf(v0, v1);
#pragma unroll
            for (int o = 16; o; o >>= 1) mx = fmaxf(mx, __shfl_xor_sync(~0u, mx, o));
            const float mold = MR[r];
            const float mnew = fmaxf(mold, mx);
            __half h0 = __float2half_rn((c0     < rows) ? __expf(v0 - mnew) : 0.f);
            __half h1 = __float2half_rn((c0 + 1 < rows) ? __expf(v1 - mnew) : 0.f);
            *(__half2*)&PH[r * 72 + c0] = __halves2half2(h0, h1);
            float ls = __half2float(h0) + __half2float(h1);
#pragma unroll
            for (int o = 16; o; o >>= 1) ls += __shfl_xor_sync(~0u, ls, o);
            if (lane == 0) {
                const float al = __expf(mold - mnew);
                AR[r] = al;
                LR[r] = LR[r] * al + ls;
                MR[r] = mnew;
            }
        }
        __syncthreads();

#pragma unroll
        for (int i = 0; i < 4; i++) {
            const float a0 = AR[om + i * 16 + g];
            const float a1 = AR[om + i * 16 + g + 8];
#pragma unroll
            for (int j = 0; j < 2; j++) {
                oacc[i][j][0] *= a0; oacc[i][j][1] *= a0;
                oacc[i][j][2] *= a1; oacc[i][j][3] *= a1;
            }
        }

#pragma unroll
        for (int ks = 0; ks < 4; ks++) {
            uint32_t af[4][4], bf[2][2];
#pragma unroll
            for (int i = 0; i < 4; i++) {
                const __half* base = &PH[(om + i * 16) * 72 + ks * 16];
                af[i][0] = *(const uint32_t*)&base[(g)     * 72 + 2 * tg];
                af[i][1] = *(const uint32_t*)&base[(g + 8) * 72 + 2 * tg];
                af[i][2] = *(const uint32_t*)&base[(g)     * 72 + 2 * tg + 8];
                af[i][3] = *(const uint32_t*)&base[(g + 8) * 72 + 2 * tg + 8];
            }
#pragma unroll
            for (int j = 0; j < 2; j++) {
                const __half* base = &VT[(on + j * 8 + g) * 72 + ks * 16];
                bf[j][0] = *(const uint32_t*)&base[2 * tg];
                bf[j][1] = *(const uint32_t*)&base[2 * tg + 8];
            }
#pragma unroll
            for (int i = 0; i < 4; i++)
#pragma unroll
                for (int j = 0; j < 2; j++)
                    MMA_F16(oacc[i][j][0], oacc[i][j][1], oacc[i][j][2], oacc[i][j][3],
                            af[i][0], af[i][1], af[i][2], af[i][3],
                            bf[j][0], bf[j][1]);
        }
        __syncthreads();
    }

    // ---- epilogue: O / l -> half (A-operand of the out-projection) ----
    __half* Ob = O + ((size_t)(b * SEQn + m0)) * 1024u + h * 64;
#pragma unroll
    for (int i = 0; i < 4; i++) {
        const int r0 = om + i * 16 + g;
        const float li0 = 1.f / LR[r0];
        const float li1 = 1.f / LR[r0 + 8];
#pragma unroll
        for (int j = 0; j < 2; j++) {
            const int c = on + j * 8 + tg * 2;
            *(__half2*)&Ob[(size_t)r0 * 1024u + c] =
                __floats2half2_rn(oacc[i][j][0] * li0, oacc[i][j][1] * li0);
            *(__half2*)&Ob[(size_t)(r0 + 8) * 1024u + c] =
                __floats2half2_rn(oacc[i][j][2] * li1, oacc[i][j][3] * li1);
        }
    }
}

// ---------------- weight transpose (fp16 rn) -------------------------------
__global__ void transpose_1024_h(const float* __restrict__ W, __half* __restrict__ Wt)
{
    __shared__ float t[32][33];
    const int bx = blockIdx.x * 32, by = blockIdx.y * 32;
    const int tx = threadIdx.x, ty = threadIdx.y;
#pragma unroll
    for (int i = 0; i < 4; i++)
        t[ty + i * 8][tx] = W[(size_t)(by + ty + i * 8) * 1024 + bx + tx];
    __syncthreads();
#pragma unroll
    for (int i = 0; i < 4; i++)
        Wt[(size_t)(bx + ty + i * 8) * 1024 + by + tx] = __float2half_rn(t[tx][ty + i * 8]);
}

// ---------------- conversion copies / trig tables ---------------------------
__global__ void half_copy(const float4* __restrict__ in, __half2* __restrict__ out, int n4)
{
    int i = blockIdx.x * blockDim.x + threadIdx.x;
    if (i < n4) {
        float4 v = in[i];
        out[2 * i]     = __floats2half2_rn(v.x, v.y);
        out[2 * i + 1] = __floats2half2_rn(v.z, v.w);
    }
}

__global__ void cs_precompute(const float* __restrict__ freqs,
                              float* __restrict__ cf, float* __restrict__ sf)
{
    int i = blockIdx.x * blockDim.x + threadIdx.x;
    if (i < 64*64*64) {
        float v = freqs[i];
        cf[i] = cosf(v);
        sf[i] = sinf(v);
    }
}

// ---------------- host launch ----------------------------------------------
extern "C" void kernel_launch(void* const* d_in, const int* in_sizes, int n_in,
                              void* d_out, int out_size)
{
    const float* x     = (const float*)d_in[0];
    const float* cond  = (const float*)d_in[1];
    const float* freqs = (const float*)d_in[2];
    const float* Wq    = (const float*)d_in[3];
    const float* Wk    = (const float*)d_in[4];
    const float* Wv    = (const float*)d_in[5];
    const float* rel   = (const float*)d_in[6];
    const float* Wo    = (const float*)d_in[7];
    const float* bo    = (const float*)d_in[8];
    const int*   memi  = (const int*)d_in[9];
    const int*   cur   = (const int*)d_in[10];
    float* out = (float*)d_out;

    float *Cf, *Sf;
    __half *Qh, *Kh, *Vt, *Oh, *Whkv, *Whq, *Who, *Ch, *Xh;
    cudaGetSymbolAddress((void**)&Qh, g_Qh);
    cudaGetSymbolAddress((void**)&Kh, g_Kh);
    cudaGetSymbolAddress((void**)&Vt, g_Vt);
    cudaGetSymbolAddress((void**)&Oh, g_Oh);
    cudaGetSymbolAddress((void**)&Whkv, g_Whkv);
    cudaGetSymbolAddress((void**)&Whq, g_Whq);
    cudaGetSymbolAddress((void**)&Who, g_Who);
    cudaGetSymbolAddress((void**)&Ch, g_Ch);
    cudaGetSymbolAddress((void**)&Xh, g_Xh);
    cudaGetSymbolAddress((void**)&Cf, g_cosf);
    cudaGetSymbolAddress((void**)&Sf, g_sinf);

    cudaFuncSetAttribute(flash_attn, cudaFuncAttributeMaxDynamicSharedMemorySize, FL_SMEM);

    // prep
    half_copy<<<(ROWS_C*DIMn/4 + 255)/256, 256>>>((const float4*)cond, (__half2*)Ch, ROWS_C*DIMn/4);
    half_copy<<<(ROWS_X*DIMn/4 + 255)/256, 256>>>((const float4*)x,    (__half2*)Xh, ROWS_X*DIMn/4);
    cs_precompute<<<(64*64*64 + 255)/256, 256>>>(freqs, Cf, Sf);
    transpose_1024_h<<<dim3(32,32), dim3(32,8)>>>(Wk, Whkv);
    transpose_1024_h<<<dim3(32,32), dim3(32,8)>>>(Wv, Whkv + (size_t)DIMn * INNERn);
    transpose_1024_h<<<dim3(32,32), dim3(32,8)>>>(Wq, Whq);
    transpose_1024_h<<<dim3(32,32), dim3(32,8)>>>(Wo, Who);

    // merged K|V projection (fp16): K bias+rotary -> half; V -> transposed half
    gemm_kv_f16<<<dim3(16, 266), 128>>>(Ch, Whkv, Kh, Vt, Cf, Sf, rel, memi, cur, ROWS_C);

    // Q projection (fp16): fused rotary + scale -> half
    gemm_q_f16<<<dim3(8, 32), 128>>>(Xh, Whq, Qh, Cf, Sf, cur, ROWS_X);

    // fused flash attention (fp16 mma), writes half O
    flash_attn<<<dim3(2, BHn), 256, FL_SMEM>>>(Qh, Kh, Vt, Oh);

    // out = O @ Wo + bo (fp16 mma, fp32 out)
    gemm_o_f16<<<dim3(8, 32), 128>>>(Oh, Who, out, bo, ROWS_X);
}

// round 16
// speedup vs baseline: 1.4823x; 1.4823x over previous
#include <cuda_runtime.h>
#include <cuda_fp16.h>
#include <cstdint>
#include <cstddef>

// ---------------- problem constants (fixed by the dataset) ----------------
#define Bn     16
#define SEQn   256
#define DIMn   1024
#define HEADSn 16
#define DHEADn 64
#define INNERn 1024
#define Mmem   8
#define TXTn   77
#define KVn    (Mmem*SEQn + TXTn)   // 2125
#define KVP    2176                 // padded kv for transposed V
#define MSn    (Mmem*SEQn)          // 2048
#define SCALEf 0.125f               // 64^-0.5

#define ROWS_X   (Bn*SEQn)          // 4096
#define ROWS_C   (Bn*KVn)           // 34000
#define BHn      (Bn*HEADSn)        // 256

// ---------------- scratch (device globals: no allocation allowed) ---------
__device__ __half g_Qh[ROWS_X * INNERn];        // rotated+scaled Q (half)
__device__ __half g_Kh[ROWS_C * INNERn];        // biased+rotated K (half)
__device__ __half g_Vt[(size_t)BHn * 64 * KVP]; // V transposed per (b,h): [d][kv]
__device__ float  g_O[ROWS_X * INNERn];         // attention output (fp32, rna)
__device__ float  g_Wto[DIMn * INNERn];         // Wo K-major tf32
__device__ __half g_Whkv[2 * DIMn * INNERn];    // [Wtk;Wtv] K-major halves
__device__ __half g_Whq[DIMn * INNERn];         // Wq K-major half
__device__ __half g_Ch[ROWS_C * DIMn];          // half(cond)
__device__ __half g_Xh[ROWS_X * DIMn];          // half(x)
__device__ float  g_cosf[64*64*64];
__device__ float  g_sinf[64*64*64];

// ---------------- helpers --------------------------------------------------
__device__ __forceinline__ uint32_t smem_u32(const void* p) {
    uint32_t a;
    asm("{ .reg .u64 t; cvta.to.shared.u64 t, %1; cvt.u32.u64 %0, t; }" : "=r"(a) : "l"(p));
    return a;
}
__device__ __forceinline__ float rna_tf32(float x) {
    float y;
    asm("cvt.rna.tf32.f32 %0, %1;" : "=f"(y) : "f"(x));
    return y;
}
__device__ __forceinline__ void rot_pair(float2& v, float bias,
                                         const float* __restrict__ cf,
                                         const float* __restrict__ sf, int fo) {
    const float t0 = v.x + bias, t1 = v.y + bias;
    v.x = t0 * cf[fo]     - t1 * sf[fo];
    v.y = t1 * cf[fo + 1] + t0 * sf[fo + 1];
}
#define MMA_TF32(d0,d1,d2,d3,a0,a1,a2,a3,b0,b1)                               \
    asm volatile(                                                             \
        "mma.sync.aligned.m16n8k8.row.col.f32.tf32.tf32.f32 "                 \
        "{%0,%1,%2,%3},{%4,%5,%6,%7},{%8,%9},{%0,%1,%2,%3};"                  \
        : "+f"(d0), "+f"(d1), "+f"(d2), "+f"(d3)                              \
        : "r"(a0), "r"(a1), "r"(a2), "r"(a3), "r"(b0), "r"(b1))
#define MMA_F16(d0,d1,d2,d3,a0,a1,a2,a3,b0,b1)                                \
    asm volatile(                                                             \
        "mma.sync.aligned.m16n8k16.row.col.f32.f16.f16.f32 "                  \
        "{%0,%1,%2,%3},{%4,%5,%6,%7},{%8,%9},{%0,%1,%2,%3};"                  \
        : "+f"(d0), "+f"(d1), "+f"(d2), "+f"(d3)                              \
        : "r"(a0), "r"(a1), "r"(a2), "r"(a3), "r"(b0), "r"(b1))
#define CP16(dst, src)     asm volatile("cp.async.cg.shared.global [%0], [%1], 16;" :: "r"(dst), "l"(src))
#define CP16P(dst, src, p) asm volatile("cp.async.cg.shared.global [%0], [%1], 16, %2;" :: "r"(dst), "l"(src), "r"(p))
#define CP_COMMIT()        asm volatile("cp.async.commit_group;" ::: "memory")
#define CP_WAIT(n)         asm volatile("cp.async.wait_group %0;" :: "n"(n) : "memory")

#define HSTR 40   // fp16 smem row stride in halves (80B): conflict-free

// ====== fp16 GEMM core loop (KV + Q projection kernels) ====================
#define F16_GEMM_BODY(Aptr, Bptr, Mv)                                          \
    auto issue = [&](int buf, int kt) {                                        \
        const int k0 = kt * 32;                                                \
        _Pragma("unroll")                                                      \
        for (int e = 0; e < 4; e++) {                                          \
            int idx = tid + e * 128;                                           \
            int row = idx >> 2, c8 = (idx & 3) * 8;                            \
            int ga = m0 + row;                                                 \
            int pa = (ga < Mv) ? 16 : 0;                                       \
            if (ga >= Mv) ga = Mv - 1;                                         \
            uint32_t da = smem_u32(&As[buf][row * HSTR + c8]);                 \
            CP16P(da, Aptr + (size_t)ga * 1024u + k0 + c8, pa);                \
            uint32_t db = smem_u32(&Bs[buf][row * HSTR + c8]);                 \
            CP16(db, Bptr + (size_t)(n0 + row) * 1024u + k0 + c8);             \
        }                                                                      \
        CP_COMMIT();                                                           \
    };                                                                         \
    issue(0, 0);                                                               \
    issue(1, 1);                                                               \
    for (int kt = 0; kt < 32; kt++) {                                          \
        const int buf = kt & 1;                                                \
        if (kt < 31) CP_WAIT(1);                                               \
        else         CP_WAIT(0);                                               \
        __syncthreads();                                                       \
        _Pragma("unroll")                                                      \
        for (int ks = 0; ks < 2; ks++) {                                       \
            uint32_t af[4][4], bf[8][2];                                       \
            _Pragma("unroll")                                                  \
            for (int i = 0; i < 4; i++) {                                      \
                const __half* base = &As[buf][(wm + i * 16) * HSTR + ks * 16]; \
                af[i][0] = *(const uint32_t*)&base[(g)     * HSTR + 2 * tg];   \
                af[i][1] = *(const uint32_t*)&base[(g + 8) * HSTR + 2 * tg];   \
                af[i][2] = *(const uint32_t*)&base[(g)     * HSTR + 2 * tg + 8];\
                af[i][3] = *(const uint32_t*)&base[(g + 8) * HSTR + 2 * tg + 8];\
            }                                                                  \
            _Pragma("unroll")                                                  \
            for (int j = 0; j < 8; j++) {                                      \
                const __half* base = &Bs[buf][(wn + j * 8 + g) * HSTR + ks * 16];\
                bf[j][0] = *(const uint32_t*)&base[2 * tg];                    \
                bf[j][1] = *(const uint32_t*)&base[2 * tg + 8];                \
            }                                                                  \
            _Pragma("unroll")                                                  \
            for (int i = 0; i < 4; i++)                                        \
                _Pragma("unroll")                                              \
                for (int j = 0; j < 8; j++)                                    \
                    MMA_F16(d[i][j][0], d[i][j][1], d[i][j][2], d[i][j][3],    \
                            af[i][0], af[i][1], af[i][2], af[i][3],            \
                            bf[j][0], bf[j][1]);                               \
        }                                                                      \
        __syncthreads();                                                       \
        if (kt + 2 < 32) issue(buf, kt + 2);                                   \
    }

// =================== fp16 GEMM: merged K|V projection ======================
__global__ __launch_bounds__(128, 2)
void gemm_kv_f16(const __half* __restrict__ A, const __half* __restrict__ Bt,
                 __half* __restrict__ Kh, __half* __restrict__ Vt,
                 const float* __restrict__ cf, const float* __restrict__ sf,
                 const float* __restrict__ rel_table,
                 const int* __restrict__ memidx, const int* __restrict__ cur,
                 int M)
{
    __shared__ __half As[2][128 * HSTR];
    __shared__ __half Bs[2][128 * HSTR];

    const int tid  = threadIdx.x;
    const int wid  = tid >> 5, lane = tid & 31;
    const int g    = lane >> 2, tg = lane & 3;
    const int wm   = (wid >> 1) * 64;
    const int wn   = (wid & 1) * 64;
    const int m0   = blockIdx.y * 128, n0 = blockIdx.x * 128;

    float d[4][8][4];
#pragma unroll
    for (int i = 0; i < 4; i++)
#pragma unroll
        for (int j = 0; j < 8; j++)
#pragma unroll
            for (int q = 0; q < 4; q++) d[i][j][q] = 0.f;

    F16_GEMM_BODY(A, Bt, M)

    // ---------------- epilogue ---------------------------------------------
    const bool kblk = (n0 < 1024);
    const int cb = kblk ? n0 : (n0 - 1024);

    const int cp = cur[0];
    const int ci = cp % 16;
    const int rs = ci % 4, cs = ci / 4, ts = cp / 16;
    const int hwarp = (n0 + wn) >> 6;

#pragma unroll
    for (int i = 0; i < 4; i++) {
        const int rA = m0 + wm + i * 16 + g;
        const int rB = rA + 8;

        float biasA = 0.f, biasB = 0.f;
        int fobA = 0, fobB = 0;
        bool tA = false, tB = false;
        if (kblk) {
            {
                const int b_ = rA / KVn, j = rA - b_ * KVn;
                if (j < MSn) {
                    const int m = j >> 8, jj = j & 255;
                    const int mi = memidx[m], mn = mi % 16;
                    const int rt = mn % 4, ct = mn / 4, tt = mi / 16;
                    const int rel = (rt - rs + 4) * 9 + (ct - cs + 4) + (tt - ts + 4) * 81;
                    biasA = rel_table[rel * HEADSn + hwarp];
                    fobA = (((rt * 16 + (jj >> 4)) << 6) + (ct * 16 + (jj & 15))) * 64;
                    tA = true;
                }
            }
            {
                const int b_ = rB / KVn, j = rB - b_ * KVn;
                if (j < MSn) {
                    const int m = j >> 8, jj = j & 255;
                    const int mi = memidx[m], mn = mi % 16;
                    const int rt = mn % 4, ct = mn / 4, tt = mi / 16;
                    const int rel = (rt - rs + 4) * 9 + (ct - cs + 4) + (tt - ts + 4) * 81;
                    biasB = rel_table[rel * HEADSn + hwarp];
                    fobB = (((rt * 16 + (jj >> 4)) << 6) + (ct * 16 + (jj & 15))) * 64;
                    tB = true;
                }
            }
        }

#pragma unroll
        for (int j = 0; j < 8; j++) {
            const int c  = cb + wn + j * 8 + tg * 2;
            const int d0 = (wn + j * 8 + tg * 2) & 63;
            float2 v0 = make_float2(d[i][j][0], d[i][j][1]);
            float2 v1 = make_float2(d[i][j][2], d[i][j][3]);
            if (kblk) {
                if (tA) rot_pair(v0, biasA, cf, sf, fobA + d0);
                if (tB) rot_pair(v1, biasB, cf, sf, fobB + d0);
                if (rA < M) *(__half2*)&Kh[(size_t)rA * 1024u + c] = __floats2half2_rn(v0.x, v0.y);
                if (rB < M) *(__half2*)&Kh[(size_t)rB * 1024u + c] = __floats2half2_rn(v1.x, v1.y);
            } else {
                const int hh = c >> 6, dd = c & 63;
                if (rA < M) {
                    const int b_ = rA / KVn, jv = rA - b_ * KVn;
                    __half* vt = Vt + ((size_t)(b_ * HEADSn + hh) * 64) * KVP + jv;
                    vt[(size_t)dd * KVP]       = __float2half_rn(v0.x);
                    vt[(size_t)(dd + 1) * KVP] = __float2half_rn(v0.y);
                }
                if (rB < M) {
                    const int b_ = rB / KVn, jv = rB - b_ * KVn;
                    __half* vt = Vt + ((size_t)(b_ * HEADSn + hh) * 64) * KVP + jv;
                    vt[(size_t)dd * KVP]       = __float2half_rn(v1.x);
                    vt[(size_t)(dd + 1) * KVP] = __float2half_rn(v1.y);
                }
            }
        }
    }
}

// =================== fp16 GEMM: Q projection (rotary+scale -> half) ========
__global__ __launch_bounds__(128, 2)
void gemm_q_f16(const __half* __restrict__ A, const __half* __restrict__ Bt,
                __half* __restrict__ Qh,
                const float* __restrict__ cf, const float* __restrict__ sf,
                const int* __restrict__ cur, int M)
{
    __shared__ __half As[2][128 * HSTR];
    __shared__ __half Bs[2][128 * HSTR];

    const int tid  = threadIdx.x;
    const int wid  = tid >> 5, lane = tid & 31;
    const int g    = lane >> 2, tg = lane & 3;
    const int wm   = (wid >> 1) * 64;
    const int wn   = (wid & 1) * 64;
    const int m0   = blockIdx.y * 128, n0 = blockIdx.x * 128;

    float d[4][8][4];
#pragma unroll
    for (int i = 0; i < 4; i++)
#pragma unroll
        for (int j = 0; j < 8; j++)
#pragma unroll
            for (int q = 0; q < 4; q++) d[i][j][q] = 0.f;

    F16_GEMM_BODY(A, Bt, M)

    const int ci = cur[0] % 16;
    const int rs = ci % 4, cs = ci / 4;

#pragma unroll
    for (int i = 0; i < 4; i++) {
        const int rA = m0 + wm + i * 16 + g;
        const int rB = rA + 8;
        int fobA, fobB;
        { const int s = rA & 255;
          fobA = (((rs * 16 + (s >> 4)) << 6) + (cs * 16 + (s & 15))) * 64; }
        { const int s = rB & 255;
          fobB = (((rs * 16 + (s >> 4)) << 6) + (cs * 16 + (s & 15))) * 64; }
#pragma unroll
        for (int j = 0; j < 8; j++) {
            const int c  = n0 + wn + j * 8 + tg * 2;
            const int d0 = (wn + j * 8 + tg * 2) & 63;
            float2 v0 = make_float2(d[i][j][0], d[i][j][1]);
            float2 v1 = make_float2(d[i][j][2], d[i][j][3]);
            rot_pair(v0, 0.f, cf, sf, fobA + d0);
            rot_pair(v1, 0.f, cf, sf, fobB + d0);
            if (rA < M) *(__half2*)&Qh[(size_t)rA * 1024u + c] =
                __floats2half2_rn(v0.x * SCALEf, v0.y * SCALEf);
            if (rB < M) *(__half2*)&Qh[(size_t)rB * 1024u + c] =
                __floats2half2_rn(v1.x * SCALEf, v1.y * SCALEf);
        }
    }
}

// =================== tf32 mma GEMM (out projection, as in R13) =============
#define SA_STR 20

__global__ __launch_bounds__(128, 2)
void gemm_o_tf32(const float* __restrict__ A, const float* __restrict__ Bt,
                 float* __restrict__ C, const float* __restrict__ bias, int M)
{
    __shared__ float As[2][128 * SA_STR];
    __shared__ float Bs[2][128 * SA_STR];

    const int tid  = threadIdx.x;
    const int wid  = tid >> 5, lane = tid & 31;
    const int g    = lane >> 2, tg = lane & 3;
    const int wm   = (wid >> 1) * 64;
    const int wn   = (wid & 1) * 64;
    const int m0   = blockIdx.y * 128, n0 = blockIdx.x * 128;

    float d[4][8][4];
#pragma unroll
    for (int i = 0; i < 4; i++)
#pragma unroll
        for (int j = 0; j < 8; j++)
#pragma unroll
            for (int q = 0; q < 4; q++) d[i][j][q] = 0.f;

    auto issue = [&](int buf, int kt) {
        const int k0 = kt * 16;
#pragma unroll
        for (int e = 0; e < 4; e++) {
            int idx = tid + e * 128;
            int row = idx >> 2, c4 = idx & 3;
            int ga = m0 + row;
            int pa = (ga < M) ? 16 : 0;
            if (ga >= M) ga = M - 1;
            uint32_t da = smem_u32(&As[buf][row * SA_STR + c4 * 4]);
            CP16P(da, A + (size_t)ga * 1024u + k0 + c4 * 4, pa);
            uint32_t db = smem_u32(&Bs[buf][row * SA_STR + c4 * 4]);
            CP16(db, Bt + (size_t)(n0 + row) * 1024u + k0 + c4 * 4);
        }
        CP_COMMIT();
    };

    issue(0, 0);
    issue(1, 1);

    for (int kt = 0; kt < 64; kt++) {
        const int buf = kt & 1;
        if (kt < 63) CP_WAIT(1);
        else         CP_WAIT(0);
        __syncthreads();

#pragma unroll
        for (int ks = 0; ks < 2; ks++) {
            uint32_t af[4][4], bf[8][2];
#pragma unroll
            for (int i = 0; i < 4; i++) {
                const float* base = &As[buf][(wm + i * 16) * SA_STR + ks * 8];
                af[i][0] = __float_as_uint(base[(g)     * SA_STR + tg]);
                af[i][1] = __float_as_uint(base[(g + 8) * SA_STR + tg]);
                af[i][2] = __float_as_uint(base[(g)     * SA_STR + tg + 4]);
                af[i][3] = __float_as_uint(base[(g + 8) * SA_STR + tg + 4]);
            }
#pragma unroll
            for (int j = 0; j < 8; j++) {
                const float* base = &Bs[buf][(wn + j * 8 + g) * SA_STR + ks * 8];
                bf[j][0] = __float_as_uint(base[tg]);
                bf[j][1] = __float_as_uint(base[tg + 4]);
            }
#pragma unroll
            for (int i = 0; i < 4; i++)
#pragma unroll
                for (int j = 0; j < 8; j++)
                    MMA_TF32(d[i][j][0], d[i][j][1], d[i][j][2], d[i][j][3],
                             af[i][0], af[i][1], af[i][2], af[i][3],
                             bf[j][0], bf[j][1]);
        }
        __syncthreads();
        if (kt + 2 < 64) issue(buf, kt + 2);
    }

#pragma unroll
    for (int i = 0; i < 4; i++) {
        const int rA = m0 + wm + i * 16 + g;
        const int rB = rA + 8;
#pragma unroll
        for (int j = 0; j < 8; j++) {
            const int c = n0 + wn + j * 8 + tg * 2;
            const float b0 = bias[c], b1 = bias[c + 1];
            float2 v0 = make_float2(d[i][j][0] + b0, d[i][j][1] + b1);
            float2 v1 = make_float2(d[i][j][2] + b0, d[i][j][3] + b1);
            if (rA < M) *(float2*)&C[(size_t)rA * 1024u + c] = v0;
            if (rB < M) *(float2*)&C[(size_t)rB * 1024u + c] = v1;
        }
    }
}

// =================== fused flash attention (fp16 mma, R13 version) =========
#define QH_O 0                         // 128 x 72 halves
#define KH_O (QH_O + 128*72*2)         // 64 x 72 halves
#define VT_O (KH_O + 64*72*2)          // 64 x 72 halves (rows = d)
#define PH_O (VT_O + 64*72*2)          // 128 x 72 halves
#define SS_O (PH_O + 128*72*2)         // 128 x 68 floats
#define MR_O (SS_O + 128*68*4)
#define LR_O (MR_O + 128*4)
#define AR_O (LR_O + 128*4)
#define FL_SMEM (AR_O + 128*4)         // 91648 bytes

#define NCHUNK ((KVn + 63) / 64)       // 34

__global__ __launch_bounds__(256, 2)
void flash_attn(const __half* __restrict__ Q, const __half* __restrict__ K,
                const __half* __restrict__ Vt, float* __restrict__ O)
{
    extern __shared__ char smc[];
    __half* QH = (__half*)(smc + QH_O);
    __half* KH = (__half*)(smc + KH_O);
    __half* VT = (__half*)(smc + VT_O);
    __half* PH = (__half*)(smc + PH_O);
    float*  SS = (float*)(smc + SS_O);
    float*  MR = (float*)(smc + MR_O);
    float*  LR = (float*)(smc + LR_O);
    float*  AR = (float*)(smc + AR_O);

    const int tid = threadIdx.x;
    const int wid = tid >> 5, lane = tid & 31;
    const int g = lane >> 2, tg = lane & 3;
    const int bh = blockIdx.y, b = bh >> 4, h = bh & 15;
    const int m0 = blockIdx.x * 128;

    const __half* Qb = Q + ((size_t)(b * SEQn + m0)) * 1024u + h * 64;
    const __half* Kb = K + ((size_t)b * KVn) * 1024u + h * 64;
    const __half* Vb = Vt + ((size_t)bh * 64) * KVP;

#pragma unroll
    for (int e = 0; e < 4; e++) {
        int idx = tid + e * 256;
        int r = idx >> 3, c8 = (idx & 7) * 8;
        uint32_t dq = smem_u32(&QH[r * 72 + c8]);
        CP16(dq, Qb + (size_t)r * 1024u + c8);
    }
    CP_COMMIT();
    if (tid < 128) { MR[tid] = -1e30f; LR[tid] = 0.f; }

    float oacc[4][2][4];
#pragma unroll
    for (int i = 0; i < 4; i++)
#pragma unroll
        for (int j = 0; j < 2; j++)
#pragma unroll
            for (int q = 0; q < 4; q++) oacc[i][j][q] = 0.f;

    const int om = (wid >> 2) * 64;
    const int on = (wid & 3) * 16;

    for (int t = 0; t < NCHUNK; t++) {
        const int kv0 = t * 64;
        const int rows = (KVn - kv0 < 64) ? (KVn - kv0) : 64;

#pragma unroll
        for (int e = 0; e < 4; e++) {
            int idx = tid + e * 256;
            int r = (idx >> 3) & 63, c8 = (idx & 7) * 8;
            if (idx < 512) {
                int kvr = kv0 + r; if (kvr >= KVn) kvr = KVn - 1;
                uint32_t dk = smem_u32(&KH[r * 72 + c8]);
                CP16(dk, Kb + (size_t)kvr * 1024u + c8);
            } else {
                uint32_t dv = smem_u32(&VT[r * 72 + c8]);
                CP16(dv, Vb + (size_t)r * KVP + kv0 + c8);
            }
        }
        CP_COMMIT();
        CP_WAIT(0);
        __syncthreads();

        float s[4][2][4];
#pragma unroll
        for (int i = 0; i < 4; i++)
#pragma unroll
            for (int j = 0; j < 2; j++)
#pragma unroll
                for (int q = 0; q < 4; q++) s[i][j][q] = 0.f;

#pragma unroll
        for (int ks = 0; ks < 4; ks++) {
            uint32_t af[4][4], bf[2][2];
#pragma unroll
            for (int i = 0; i < 4; i++) {
                const __half* base = &QH[(om + i * 16) * 72 + ks * 16];
                af[i][0] = *(const uint32_t*)&base[(g)     * 72 + 2 * tg];
                af[i][1] = *(const uint32_t*)&base[(g + 8) * 72 + 2 * tg];
                af[i][2] = *(const uint32_t*)&base[(g)     * 72 + 2 * tg + 8];
                af[i][3] = *(const uint32_t*)&base[(g + 8) * 72 + 2 * tg + 8];
            }
#pragma unroll
            for (int j = 0; j < 2; j++) {
                const __half* base = &KH[(on + j * 8 + g) * 72 + ks * 16];
                bf[j][0] = *(const uint32_t*)&base[2 * tg];
                bf[j][1] = *(const uint32_t*)&base[2 * tg + 8];
            }
#pragma unroll
            for (int i = 0; i < 4; i++)
#pragma unroll
                for (int j = 0; j < 2; j++)
                    MMA_F16(s[i][j][0], s[i][j][1], s[i][j][2], s[i][j][3],
                            af[i][0], af[i][1], af[i][2], af[i][3],
                            bf[j][0], bf[j][1]);
        }
#pragma unroll
        for (int i = 0; i < 4; i++) {
            const int r0 = om + i * 16 + g;
#pragma unroll
            for (int j = 0; j < 2; j++) {
                const int c = on + j * 8 + tg * 2;
                SS[r0 * 68 + c]           = s[i][j][0];
                SS[r0 * 68 + c + 1]       = s[i][j][1];
                SS[(r0 + 8) * 68 + c]     = s[i][j][2];
                SS[(r0 + 8) * 68 + c + 1] = s[i][j][3];
            }
        }
        __syncthreads();

#pragma unroll 4
        for (int rr = 0; rr < 16; rr++) {
            const int r = wid * 16 + rr;
            const int c0 = lane * 2;
            float v0 = (c0     < rows) ? SS[r * 68 + c0]     : -1e30f;
            float v1 = (c0 + 1 < rows) ? SS[r * 68 + c0 + 1] : -1e30f;
            float mx = fmaxf(v0, v1);
#pragma unroll
            for (int o = 16; o; o >>= 1) mx = fmaxf(mx, __shfl_xor_sync(~0u, mx, o));
            const float mold = MR[r];
            const float mnew = fmaxf(mold, mx);
            __half h0 = __float2half_rn((c0     < rows) ? __expf(v0 - mnew) : 0.f);
            __half h1 = __float2half_rn((c0 + 1 < rows) ? __expf(v1 - mnew) : 0.f);
            *(__half2*)&PH[r * 72 + c0] = __halves2half2(h0, h1);
            float ls = __half2float(h0) + __half2float(h1);
#pragma unroll
            for (int o = 16; o; o >>= 1) ls += __shfl_xor_sync(~0u, ls, o);
            if (lane == 0) {
                const float al = __expf(mold - mnew);
                AR[r] = al;
                LR[r] = LR[r] * al + ls;
                MR[r] = mnew;
            }
        }
        __syncthreads();

#pragma unroll
        for (int i = 0; i < 4; i++) {
            const float a0 = AR[om + i * 16 + g];
            const float a1 = AR[om + i * 16 + g + 8];
#pragma unroll
            for (int j = 0; j < 2; j++) {
                oacc[i][j][0] *= a0; oacc[i][j][1] *= a0;
                oacc[i][j][2] *= a1; oacc[i][j][3] *= a1;
            }
        }

#pragma unroll
        for (int ks = 0; ks < 4; ks++) {
            uint32_t af[4][4], bf[2][2];
#pragma unroll
            for (int i = 0; i < 4; i++) {
                const __half* base = &PH[(om + i * 16) * 72 + ks * 16];
                af[i][0] = *(const uint32_t*)&base[(g)     * 72 + 2 * tg];
                af[i][1] = *(const uint32_t*)&base[(g + 8) * 72 + 2 * tg];
                af[i][2] = *(const uint32_t*)&base[(g)     * 72 + 2 * tg + 8];
                af[i][3] = *(const uint32_t*)&base[(g + 8) * 72 + 2 * tg + 8];
            }
#pragma unroll
            for (int j = 0; j < 2; j++) {
                const __half* base = &VT[(on + j * 8 + g) * 72 + ks * 16];
                bf[j][0] = *(const uint32_t*)&base[2 * tg];
                bf[j][1] = *(const uint32_t*)&base[2 * tg + 8];
            }
#pragma unroll
            for (int i = 0; i < 4; i++)
#pragma unroll
                for (int j = 0; j < 2; j++)
                    MMA_F16(oacc[i][j][0], oacc[i][j][1], oacc[i][j][2], oacc[i][j][3],
                            af[i][0], af[i][1], af[i][2], af[i][3],
                            bf[j][0], bf[j][1]);
        }
        __syncthreads();
    }

    // ---- epilogue: O / l, rna-round for tf32 out-projection ----
    float* Ob = O + ((size_t)(b * SEQn + m0)) * 1024u + h * 64;
#pragma unroll
    for (int i = 0; i < 4; i++) {
        const int r0 = om + i * 16 + g;
        const float li0 = 1.f / LR[r0];
        const float li1 = 1.f / LR[r0 + 8];
#pragma unroll
        for (int j = 0; j < 2; j++) {
            const int c = on + j * 8 + tg * 2;
            float2 v0 = make_float2(rna_tf32(oacc[i][j][0] * li0), rna_tf32(oacc[i][j][1] * li0));
            float2 v1 = make_float2(rna_tf32(oacc[i][j][2] * li1), rna_tf32(oacc[i][j][3] * li1));
            *(float2*)&Ob[(size_t)r0 * 1024u + c]       = v0;
            *(float2*)&Ob[(size_t)(r0 + 8) * 1024u + c] = v1;
        }
    }
}

// ---------------- weight transpose (fp32 rna / fp16 rn) --------------------
__global__ void transpose_1024(const float* __restrict__ W, float* __restrict__ Wt)
{
    __shared__ float t[32][33];
    const int bx = blockIdx.x * 32, by = blockIdx.y * 32;
    const int tx = threadIdx.x, ty = threadIdx.y;
#pragma unroll
    for (int i = 0; i < 4; i++)
        t[ty + i * 8][tx] = W[(size_t)(by + ty + i * 8) * 1024 + bx + tx];
    __syncthreads();
#pragma unroll
    for (int i = 0; i < 4; i++)
        Wt[(size_t)(bx + ty + i * 8) * 1024 + by + tx] = rna_tf32(t[tx][ty + i * 8]);
}

__global__ void transpose_1024_h(const float* __restrict__ W, __half* __restrict__ Wt)
{
    __shared__ float t[32][33];
    const int bx = blockIdx.x * 32, by = blockIdx.y * 32;
    const int tx = threadIdx.x, ty = threadIdx.y;
#pragma unroll
    for (int i = 0; i < 4; i++)
        t[ty + i * 8][tx] = W[(size_t)(by + ty + i * 8) * 1024 + bx + tx];
    __syncthreads();
#pragma unroll
    for (int i = 0; i < 4; i++)
        Wt[(size_t)(bx + ty + i * 8) * 1024 + by + tx] = __float2half_rn(t[tx][ty + i * 8]);
}

// ---------------- conversion copies / trig tables ---------------------------
__global__ void half_copy(const float4* __restrict__ in, __half2* __restrict__ out, int n4)
{
    int i = blockIdx.x * blockDim.x + threadIdx.x;
    if (i < n4) {
        float4 v = in[i];
        out[2 * i]     = __floats2half2_rn(v.x, v.y);
        out[2 * i + 1] = __floats2half2_rn(v.z, v.w);
    }
}

__global__ void cs_precompute(const float* __restrict__ freqs,
                              float* __restrict__ cf, float* __restrict__ sf)
{
    int i = blockIdx.x * blockDim.x + threadIdx.x;
    if (i < 64*64*64) {
        float v = freqs[i];
        cf[i] = cosf(v);
        sf[i] = sinf(v);
    }
}

// ---------------- host launch ----------------------------------------------
extern "C" void kernel_launch(void* const* d_in, const int* in_sizes, int n_in,
                              void* d_out, int out_size)
{
    const float* x     = (const float*)d_in[0];
    const float* cond  = (const float*)d_in[1];
    const float* freqs = (const float*)d_in[2];
    const float* Wq    = (const float*)d_in[3];
    const float* Wk    = (const float*)d_in[4];
    const float* Wv    = (const float*)d_in[5];
    const float* rel   = (const float*)d_in[6];
    const float* Wo    = (const float*)d_in[7];
    const float* bo    = (const float*)d_in[8];
    const int*   memi  = (const int*)d_in[9];
    const int*   cur   = (const int*)d_in[10];
    float* out = (float*)d_out;

    float *Ob, *Wto, *Cf, *Sf;
    __half *Qh, *Kh, *Vt, *Whkv, *Whq, *Ch, *Xh;
    cudaGetSymbolAddress((void**)&Qh, g_Qh);
    cudaGetSymbolAddress((void**)&Kh, g_Kh);
    cudaGetSymbolAddress((void**)&Vt, g_Vt);
    cudaGetSymbolAddress((void**)&Ob, g_O);
    cudaGetSymbolAddress((void**)&Wto, g_Wto);
    cudaGetSymbolAddress((void**)&Whkv, g_Whkv);
    cudaGetSymbolAddress((void**)&Whq, g_Whq);
    cudaGetSymbolAddress((void**)&Ch, g_Ch);
    cudaGetSymbolAddress((void**)&Xh, g_Xh);
    cudaGetSymbolAddress((void**)&Cf, g_cosf);
    cudaGetSymbolAddress((void**)&Sf, g_sinf);

    cudaFuncSetAttribute(flash_attn, cudaFuncAttributeMaxDynamicSharedMemorySize, FL_SMEM);

    // prep
    half_copy<<<(ROWS_C*DIMn/4 + 255)/256, 256>>>((const float4*)cond, (__half2*)Ch, ROWS_C*DIMn/4);
    half_copy<<<(ROWS_X*DIMn/4 + 255)/256, 256>>>((const float4*)x,    (__half2*)Xh, ROWS_X*DIMn/4);
    cs_precompute<<<(64*64*64 + 255)/256, 256>>>(freqs, Cf, Sf);
    transpose_1024_h<<<dim3(32,32), dim3(32,8)>>>(Wk, Whkv);
    transpose_1024_h<<<dim3(32,32), dim3(32,8)>>>(Wv, Whkv + (size_t)DIMn * INNERn);
    transpose_1024_h<<<dim3(32,32), dim3(32,8)>>>(Wq, Whq);
    transpose_1024<<<dim3(32,32), dim3(32,8)>>>(Wo, Wto);

    // merged K|V projection (fp16): K bias+rotary -> half; V -> transposed half
    gemm_kv_f16<<<dim3(16, 266), 128>>>(Ch, Whkv, Kh, Vt, Cf, Sf, rel, memi, cur, ROWS_C);

    // Q projection (fp16): fused rotary + scale -> half
    gemm_q_f16<<<dim3(8, 32), 128>>>(Xh, Whq, Qh, Cf, Sf, cur, ROWS_X);

    // fused flash attention (fp16 mma), writes fp32 O (rna) — R13 version
    flash_attn<<<dim3(2, BHn), 256, FL_SMEM>>>(Qh, Kh, Vt, Ob);

    // out = O @ Wo + bo (tf32, as in R13)
    gemm_o_tf32<<<dim3(8, 32), 128>>>(Ob, Wto, out, bo, ROWS_X);
}

// round 17
// speedup vs baseline: 1.8518x; 1.2493x over previous
#include <cuda_runtime.h>
#include <cuda_fp16.h>
#include <cstdint>
#include <cstddef>

// ---------------- problem constants (fixed by the dataset) ----------------
#define Bn     16
#define SEQn   256
#define DIMn   1024
#define HEADSn 16
#define DHEADn 64
#define INNERn 1024
#define Mmem   8
#define TXTn   77
#define KVn    (Mmem*SEQn + TXTn)   // 2125
#define KVP    2176                 // padded kv for transposed V
#define MSn    (Mmem*SEQn)          // 2048
#define SCALEf 0.125f               // 64^-0.5

#define ROWS_X   (Bn*SEQn)          // 4096
#define ROWS_C   (Bn*KVn)           // 34000
#define BHn      (Bn*HEADSn)        // 256

// ---------------- scratch (device globals: no allocation allowed) ---------
__device__ __half g_Qh[ROWS_X * INNERn];        // rotated+scaled Q (half)
__device__ __half g_Kh[ROWS_C * INNERn];        // biased+rotated K (half)
__device__ __half g_Vt[(size_t)BHn * 64 * KVP]; // V transposed per (b,h): [d][kv]
__device__ float  g_O[ROWS_X * INNERn];         // attention output (fp32, rna)
__device__ float  g_Wto[DIMn * INNERn];         // Wo K-major tf32
__device__ __half g_Whkv[2 * DIMn * INNERn];    // [Wtk;Wtv] K-major halves
__device__ __half g_Whq[DIMn * INNERn];         // Wq K-major half
__device__ __half g_Ch[ROWS_C * DIMn];          // half(cond)
__device__ __half g_Xh[ROWS_X * DIMn];          // half(x)
__device__ float  g_cosf[64*64*64];
__device__ float  g_sinf[64*64*64];

// ---------------- helpers --------------------------------------------------
__device__ __forceinline__ uint32_t smem_u32(const void* p) {
    uint32_t a;
    asm("{ .reg .u64 t; cvta.to.shared.u64 t, %1; cvt.u32.u64 %0, t; }" : "=r"(a) : "l"(p));
    return a;
}
__device__ __forceinline__ float rna_tf32(float x) {
    float y;
    asm("cvt.rna.tf32.f32 %0, %1;" : "=f"(y) : "f"(x));
    return y;
}
__device__ __forceinline__ void rot_pair(float2& v, float bias,
                                         const float* __restrict__ cf,
                                         const float* __restrict__ sf, int fo) {
    const float t0 = v.x + bias, t1 = v.y + bias;
    v.x = t0 * cf[fo]     - t1 * sf[fo];
    v.y = t1 * cf[fo + 1] + t0 * sf[fo + 1];
}
#define MMA_TF32(d0,d1,d2,d3,a0,a1,a2,a3,b0,b1)                               \
    asm volatile(                                                             \
        "mma.sync.aligned.m16n8k8.row.col.f32.tf32.tf32.f32 "                 \
        "{%0,%1,%2,%3},{%4,%5,%6,%7},{%8,%9},{%0,%1,%2,%3};"                  \
        : "+f"(d0), "+f"(d1), "+f"(d2), "+f"(d3)                              \
        : "r"(a0), "r"(a1), "r"(a2), "r"(a3), "r"(b0), "r"(b1))
#define MMA_F16(d0,d1,d2,d3,a0,a1,a2,a3,b0,b1)                                \
    asm volatile(                                                             \
        "mma.sync.aligned.m16n8k16.row.col.f32.f16.f16.f32 "                  \
        "{%0,%1,%2,%3},{%4,%5,%6,%7},{%8,%9},{%0,%1,%2,%3};"                  \
        : "+f"(d0), "+f"(d1), "+f"(d2), "+f"(d3)                              \
        : "r"(a0), "r"(a1), "r"(a2), "r"(a3), "r"(b0), "r"(b1))
#define CP16(dst, src)     asm volatile("cp.async.cg.shared.global [%0], [%1], 16;" :: "r"(dst), "l"(src))
#define CP16P(dst, src, p) asm volatile("cp.async.cg.shared.global [%0], [%1], 16, %2;" :: "r"(dst), "l"(src), "r"(p))
#define CP_COMMIT()        asm volatile("cp.async.commit_group;" ::: "memory")
#define CP_WAIT(n)         asm volatile("cp.async.wait_group %0;" :: "n"(n) : "memory")

#define HSTR 40   // fp16 smem row stride in halves (80B): conflict-free

// ====== fp16 GEMM core loop (KV + Q projection kernels) ====================
#define F16_GEMM_BODY(Aptr, Bptr, Mv)                                          \
    auto issue = [&](int buf, int kt) {                                        \
        const int k0 = kt * 32;                                                \
        _Pragma("unroll")                                                      \
        for (int e = 0; e < 4; e++) {                                          \
            int idx = tid + e * 128;                                           \
            int row = idx >> 2, c8 = (idx & 3) * 8;                            \
            int ga = m0 + row;                                                 \
            int pa = (ga < Mv) ? 16 : 0;                                       \
            if (ga >= Mv) ga = Mv - 1;                                         \
            uint32_t da = smem_u32(&As[buf][row * HSTR + c8]);                 \
            CP16P(da, Aptr + (size_t)ga * 1024u + k0 + c8, pa);                \
            uint32_t db = smem_u32(&Bs[buf][row * HSTR + c8]);                 \
            CP16(db, Bptr + (size_t)(n0 + row) * 1024u + k0 + c8);             \
        }                                                                      \
        CP_COMMIT();                                                           \
    };                                                                         \
    issue(0, 0);                                                               \
    issue(1, 1);                                                               \
    for (int kt = 0; kt < 32; kt++) {                                          \
        const int buf = kt & 1;                                                \
        if (kt < 31) CP_WAIT(1);                                               \
        else         CP_WAIT(0);                                               \
        __syncthreads();                                                       \
        _Pragma("unroll")                                                      \
        for (int ks = 0; ks < 2; ks++) {                                       \
            uint32_t af[4][4], bf[8][2];                                       \
            _Pragma("unroll")                                                  \
            for (int i = 0; i < 4; i++) {                                      \
                const __half* base = &As[buf][(wm + i * 16) * HSTR + ks * 16]; \
                af[i][0] = *(const uint32_t*)&base[(g)     * HSTR + 2 * tg];   \
                af[i][1] = *(const uint32_t*)&base[(g + 8) * HSTR + 2 * tg];   \
                af[i][2] = *(const uint32_t*)&base[(g)     * HSTR + 2 * tg + 8];\
                af[i][3] = *(const uint32_t*)&base[(g + 8) * HSTR + 2 * tg + 8];\
            }                                                                  \
            _Pragma("unroll")                                                  \
            for (int j = 0; j < 8; j++) {                                      \
                const __half* base = &Bs[buf][(wn + j * 8 + g) * HSTR + ks * 16];\
                bf[j][0] = *(const uint32_t*)&base[2 * tg];                    \
                bf[j][1] = *(const uint32_t*)&base[2 * tg + 8];                \
            }                                                                  \
            _Pragma("unroll")                                                  \
            for (int i = 0; i < 4; i++)                                        \
                _Pragma("unroll")                                              \
                for (int j = 0; j < 8; j++)                                    \
                    MMA_F16(d[i][j][0], d[i][j][1], d[i][j][2], d[i][j][3],    \
                            af[i][0], af[i][1], af[i][2], af[i][3],            \
                            bf[j][0], bf[j][1]);                               \
        }                                                                      \
        __syncthreads();                                                       \
        if (kt + 2 < 32) issue(buf, kt + 2);                                   \
    }

// =================== fp16 GEMM: merged K|V projection ======================
__global__ __launch_bounds__(128, 2)
void gemm_kv_f16(const __half* __restrict__ A, const __half* __restrict__ Bt,
                 __half* __restrict__ Kh, __half* __restrict__ Vt,
                 const float* __restrict__ cf, const float* __restrict__ sf,
                 const float* __restrict__ rel_table,
                 const int* __restrict__ memidx, const int* __restrict__ cur,
                 int M)
{
    __shared__ __half As[2][128 * HSTR];
    __shared__ __half Bs[2][128 * HSTR];

    const int tid  = threadIdx.x;
    const int wid  = tid >> 5, lane = tid & 31;
    const int g    = lane >> 2, tg = lane & 3;
    const int wm   = (wid >> 1) * 64;
    const int wn   = (wid & 1) * 64;
    const int m0   = blockIdx.y * 128, n0 = blockIdx.x * 128;

    float d[4][8][4];
#pragma unroll
    for (int i = 0; i < 4; i++)
#pragma unroll
        for (int j = 0; j < 8; j++)
#pragma unroll
            for (int q = 0; q < 4; q++) d[i][j][q] = 0.f;

    F16_GEMM_BODY(A, Bt, M)

    // ---------------- epilogue ---------------------------------------------
    const bool kblk = (n0 < 1024);
    const int cb = kblk ? n0 : (n0 - 1024);

    const int cp = cur[0];
    const int ci = cp % 16;
    const int rs = ci % 4, cs = ci / 4, ts = cp / 16;
    const int hwarp = (n0 + wn) >> 6;

#pragma unroll
    for (int i = 0; i < 4; i++) {
        const int rA = m0 + wm + i * 16 + g;
        const int rB = rA + 8;

        float biasA = 0.f, biasB = 0.f;
        int fobA = 0, fobB = 0;
        bool tA = false, tB = false;
        if (kblk) {
            {
                const int b_ = rA / KVn, j = rA - b_ * KVn;
                if (j < MSn) {
                    const int m = j >> 8, jj = j & 255;
                    const int mi = memidx[m], mn = mi % 16;
                    const int rt = mn % 4, ct = mn / 4, tt = mi / 16;
                    const int rel = (rt - rs + 4) * 9 + (ct - cs + 4) + (tt - ts + 4) * 81;
                    biasA = rel_table[rel * HEADSn + hwarp];
                    fobA = (((rt * 16 + (jj >> 4)) << 6) + (ct * 16 + (jj & 15))) * 64;
                    tA = true;
                }
            }
            {
                const int b_ = rB / KVn, j = rB - b_ * KVn;
                if (j < MSn) {
                    const int m = j >> 8, jj = j & 255;
                    const int mi = memidx[m], mn = mi % 16;
                    const int rt = mn % 4, ct = mn / 4, tt = mi / 16;
                    const int rel = (rt - rs + 4) * 9 + (ct - cs + 4) + (tt - ts + 4) * 81;
                    biasB = rel_table[rel * HEADSn + hwarp];
                    fobB = (((rt * 16 + (jj >> 4)) << 6) + (ct * 16 + (jj & 15))) * 64;
                    tB = true;
                }
            }
        }

#pragma unroll
        for (int j = 0; j < 8; j++) {
            const int c  = cb + wn + j * 8 + tg * 2;
            const int d0 = (wn + j * 8 + tg * 2) & 63;
            float2 v0 = make_float2(d[i][j][0], d[i][j][1]);
            float2 v1 = make_float2(d[i][j][2], d[i][j][3]);
            if (kblk) {
                if (tA) rot_pair(v0, biasA, cf, sf, fobA + d0);
                if (tB) rot_pair(v1, biasB, cf, sf, fobB + d0);
                if (rA < M) *(__half2*)&Kh[(size_t)rA * 1024u + c] = __floats2half2_rn(v0.x, v0.y);
                if (rB < M) *(__half2*)&Kh[(size_t)rB * 1024u + c] = __floats2half2_rn(v1.x, v1.y);
            } else {
                const int hh = c >> 6, dd = c & 63;
                if (rA < M) {
                    const int b_ = rA / KVn, jv = rA - b_ * KVn;
                    __half* vt = Vt + ((size_t)(b_ * HEADSn + hh) * 64) * KVP + jv;
                    vt[(size_t)dd * KVP]       = __float2half_rn(v0.x);
                    vt[(size_t)(dd + 1) * KVP] = __float2half_rn(v0.y);
                }
                if (rB < M) {
                    const int b_ = rB / KVn, jv = rB - b_ * KVn;
                    __half* vt = Vt + ((size_t)(b_ * HEADSn + hh) * 64) * KVP + jv;
                    vt[(size_t)dd * KVP]       = __float2half_rn(v1.x);
                    vt[(size_t)(dd + 1) * KVP] = __float2half_rn(v1.y);
                }
            }
        }
    }
}

// =================== fp16 GEMM: Q projection (rotary+scale -> half) ========
__global__ __launch_bounds__(128, 2)
void gemm_q_f16(const __half* __restrict__ A, const __half* __restrict__ Bt,
                __half* __restrict__ Qh,
                const float* __restrict__ cf, const float* __restrict__ sf,
                const int* __restrict__ cur, int M)
{
    __shared__ __half As[2][128 * HSTR];
    __shared__ __half Bs[2][128 * HSTR];

    const int tid  = threadIdx.x;
    const int wid  = tid >> 5, lane = tid & 31;
    const int g    = lane >> 2, tg = lane & 3;
    const int wm   = (wid >> 1) * 64;
    const int wn   = (wid & 1) * 64;
    const int m0   = blockIdx.y * 128, n0 = blockIdx.x * 128;

    float d[4][8][4];
#pragma unroll
    for (int i = 0; i < 4; i++)
#pragma unroll
        for (int j = 0; j < 8; j++)
#pragma unroll
            for (int q = 0; q < 4; q++) d[i][j][q] = 0.f;

    F16_GEMM_BODY(A, Bt, M)

    const int ci = cur[0] % 16;
    const int rs = ci % 4, cs = ci / 4;

#pragma unroll
    for (int i = 0; i < 4; i++) {
        const int rA = m0 + wm + i * 16 + g;
        const int rB = rA + 8;
        int fobA, fobB;
        { const int s = rA & 255;
          fobA = (((rs * 16 + (s >> 4)) << 6) + (cs * 16 + (s & 15))) * 64; }
        { const int s = rB & 255;
          fobB = (((rs * 16 + (s >> 4)) << 6) + (cs * 16 + (s & 15))) * 64; }
#pragma unroll
        for (int j = 0; j < 8; j++) {
            const int c  = n0 + wn + j * 8 + tg * 2;
            const int d0 = (wn + j * 8 + tg * 2) & 63;
            float2 v0 = make_float2(d[i][j][0], d[i][j][1]);
            float2 v1 = make_float2(d[i][j][2], d[i][j][3]);
            rot_pair(v0, 0.f, cf, sf, fobA + d0);
            rot_pair(v1, 0.f, cf, sf, fobB + d0);
            if (rA < M) *(__half2*)&Qh[(size_t)rA * 1024u + c] =
                __floats2half2_rn(v0.x * SCALEf, v0.y * SCALEf);
            if (rB < M) *(__half2*)&Qh[(size_t)rB * 1024u + c] =
                __floats2half2_rn(v1.x * SCALEf, v1.y * SCALEf);
        }
    }
}

// =================== tf32 mma GEMM (out projection) ========================
#define SA_STR 20

__global__ __launch_bounds__(128, 2)
void gemm_o_tf32(const float* __restrict__ A, const float* __restrict__ Bt,
                 float* __restrict__ C, const float* __restrict__ bias, int M)
{
    __shared__ float As[2][128 * SA_STR];
    __shared__ float Bs[2][128 * SA_STR];

    const int tid  = threadIdx.x;
    const int wid  = tid >> 5, lane = tid & 31;
    const int g    = lane >> 2, tg = lane & 3;
    const int wm   = (wid >> 1) * 64;
    const int wn   = (wid & 1) * 64;
    const int m0   = blockIdx.y * 128, n0 = blockIdx.x * 128;

    float d[4][8][4];
#pragma unroll
    for (int i = 0; i < 4; i++)
#pragma unroll
        for (int j = 0; j < 8; j++)
#pragma unroll
            for (int q = 0; q < 4; q++) d[i][j][q] = 0.f;

    auto issue = [&](int buf, int kt) {
        const int k0 = kt * 16;
#pragma unroll
        for (int e = 0; e < 4; e++) {
            int idx = tid + e * 128;
            int row = idx >> 2, c4 = idx & 3;
            int ga = m0 + row;
            int pa = (ga < M) ? 16 : 0;
            if (ga >= M) ga = M - 1;
            uint32_t da = smem_u32(&As[buf][row * SA_STR + c4 * 4]);
            CP16P(da, A + (size_t)ga * 1024u + k0 + c4 * 4, pa);
            uint32_t db = smem_u32(&Bs[buf][row * SA_STR + c4 * 4]);
            CP16(db, Bt + (size_t)(n0 + row) * 1024u + k0 + c4 * 4);
        }
        CP_COMMIT();
    };

    issue(0, 0);
    issue(1, 1);

    for (int kt = 0; kt < 64; kt++) {
        const int buf = kt & 1;
        if (kt < 63) CP_WAIT(1);
        else         CP_WAIT(0);
        __syncthreads();

#pragma unroll
        for (int ks = 0; ks < 2; ks++) {
            uint32_t af[4][4], bf[8][2];
#pragma unroll
            for (int i = 0; i < 4; i++) {
                const float* base = &As[buf][(wm + i * 16) * SA_STR + ks * 8];
                af[i][0] = __float_as_uint(base[(g)     * SA_STR + tg]);
                af[i][1] = __float_as_uint(base[(g + 8) * SA_STR + tg]);
                af[i][2] = __float_as_uint(base[(g)     * SA_STR + tg + 4]);
                af[i][3] = __float_as_uint(base[(g + 8) * SA_STR + tg + 4]);
            }
#pragma unroll
            for (int j = 0; j < 8; j++) {
                const float* base = &Bs[buf][(wn + j * 8 + g) * SA_STR + ks * 8];
                bf[j][0] = __float_as_uint(base[tg]);
                bf[j][1] = __float_as_uint(base[tg + 4]);
            }
#pragma unroll
            for (int i = 0; i < 4; i++)
#pragma unroll
                for (int j = 0; j < 8; j++)
                    MMA_TF32(d[i][j][0], d[i][j][1], d[i][j][2], d[i][j][3],
                             af[i][0], af[i][1], af[i][2], af[i][3],
                             bf[j][0], bf[j][1]);
        }
        __syncthreads();
        if (kt + 2 < 64) issue(buf, kt + 2);
    }

#pragma unroll
    for (int i = 0; i < 4; i++) {
        const int rA = m0 + wm + i * 16 + g;
        const int rB = rA + 8;
#pragma unroll
        for (int j = 0; j < 8; j++) {
            const int c = n0 + wn + j * 8 + tg * 2;
            const float b0 = bias[c], b1 = bias[c + 1];
            float2 v0 = make_float2(d[i][j][0] + b0, d[i][j][1] + b1);
            float2 v1 = make_float2(d[i][j][2] + b0, d[i][j][3] + b1);
            if (rA < M) *(float2*)&C[(size_t)rA * 1024u + c] = v0;
            if (rB < M) *(float2*)&C[(size_t)rB * 1024u + c] = v1;
        }
    }
}

// =================== fused flash attention (fp16 mma, register softmax) ====
// Fragment-resident softmax: quad shuffles reduce each row's 16 warp-local
// cols; 4 partials/row combined through small smem arrays (PM/PL).
#define QH_O 0                          // 128 x 72 halves
#define KH_O (QH_O + 128*72*2)          // 64 x 72 halves
#define VT_O (KH_O + 64*72*2)           // 64 x 72 halves (rows = d)
#define PH_O (VT_O + 64*72*2)           // 128 x 72 halves (P)
#define PM_O (PH_O + 128*72*2)          // 4 x 128 floats (max partials)
#define PL_O (PM_O + 4*128*4)           // 4 x 128 floats (sum partials)
#define MR_O (PL_O + 4*128*4)           // 128 floats
#define LR_O (MR_O + 128*4)             // 128 floats
#define FL_SMEM (LR_O + 128*4)          // 60416 bytes

#define NCHUNK ((KVn + 63) / 64)        // 34

__global__ __launch_bounds__(256, 2)
void flash_attn(const __half* __restrict__ Q, const __half* __restrict__ K,
                const __half* __restrict__ Vt, float* __restrict__ O)
{
    extern __shared__ char smc[];
    __half* QH = (__half*)(smc + QH_O);
    __half* KH = (__half*)(smc + KH_O);
    __half* VT = (__half*)(smc + VT_O);
    __half* PH = (__half*)(smc + PH_O);
    float*  PM = (float*)(smc + PM_O);
    float*  PL = (float*)(smc + PL_O);
    float*  MR = (float*)(smc + MR_O);
    float*  LR = (float*)(smc + LR_O);

    const int tid = threadIdx.x;
    const int wid = tid >> 5, lane = tid & 31;
    const int g = lane >> 2, tg = lane & 3;
    const int bh = blockIdx.y, b = bh >> 4, h = bh & 15;
    const int m0 = blockIdx.x * 128;

    const __half* Qb = Q + ((size_t)(b * SEQn + m0)) * 1024u + h * 64;
    const __half* Kb = K + ((size_t)b * KVn) * 1024u + h * 64;
    const __half* Vb = Vt + ((size_t)bh * 64) * KVP;

#pragma unroll
    for (int e = 0; e < 4; e++) {
        int idx = tid + e * 256;
        int r = idx >> 3, c8 = (idx & 7) * 8;
        uint32_t dq = smem_u32(&QH[r * 72 + c8]);
        CP16(dq, Qb + (size_t)r * 1024u + c8);
    }
    CP_COMMIT();
    if (tid < 128) { MR[tid] = -1e30f; LR[tid] = 0.f; }

    float oacc[4][2][4];
#pragma unroll
    for (int i = 0; i < 4; i++)
#pragma unroll
        for (int j = 0; j < 2; j++)
#pragma unroll
            for (int q = 0; q < 4; q++) oacc[i][j][q] = 0.f;

    const int om = (wid >> 2) * 64;    // warp m offset
    const int on = (wid & 3) * 16;     // warp n offset (chunk-local kv cols)
    const int wq = wid & 3;            // n-warp index (partial slot)

    for (int t = 0; t < NCHUNK; t++) {
        const int kv0 = t * 64;
        const int rows = (KVn - kv0 < 64) ? (KVn - kv0) : 64;

        // ---- load K (64x64h) + Vt (64x64h) chunk ----
#pragma unroll
        for (int e = 0; e < 4; e++) {
            int idx = tid + e * 256;
            int r = (idx >> 3) & 63, c8 = (idx & 7) * 8;
            if (idx < 512) {
                int kvr = kv0 + r; if (kvr >= KVn) kvr = KVn - 1;
                uint32_t dk = smem_u32(&KH[r * 72 + c8]);
                CP16(dk, Kb + (size_t)kvr * 1024u + c8);
            } else {
                uint32_t dv = smem_u32(&VT[r * 72 + c8]);
                CP16(dv, Vb + (size_t)r * KVP + kv0 + c8);
            }
        }
        CP_COMMIT();
        CP_WAIT(0);
        __syncthreads();

        // ---- S = Q @ K^T ----
        float s[4][2][4];
#pragma unroll
        for (int i = 0; i < 4; i++)
#pragma unroll
            for (int j = 0; j < 2; j++)
#pragma unroll
                for (int q = 0; q < 4; q++) s[i][j][q] = 0.f;

#pragma unroll
        for (int ks = 0; ks < 4; ks++) {
            uint32_t af[4][4], bf[2][2];
#pragma unroll
            for (int i = 0; i < 4; i++) {
                const __half* base = &QH[(om + i * 16) * 72 + ks * 16];
                af[i][0] = *(const uint32_t*)&base[(g)     * 72 + 2 * tg];
                af[i][1] = *(const uint32_t*)&base[(g + 8) * 72 + 2 * tg];
                af[i][2] = *(const uint32_t*)&base[(g)     * 72 + 2 * tg + 8];
                af[i][3] = *(const uint32_t*)&base[(g + 8) * 72 + 2 * tg + 8];
            }
#pragma unroll
            for (int j = 0; j < 2; j++) {
                const __half* base = &KH[(on + j * 8 + g) * 72 + ks * 16];
                bf[j][0] = *(const uint32_t*)&base[2 * tg];
                bf[j][1] = *(const uint32_t*)&base[2 * tg + 8];
            }
#pragma unroll
            for (int i = 0; i < 4; i++)
#pragma unroll
                for (int j = 0; j < 2; j++)
                    MMA_F16(s[i][j][0], s[i][j][1], s[i][j][2], s[i][j][3],
                            af[i][0], af[i][1], af[i][2], af[i][3],
                            bf[j][0], bf[j][1]);
        }

        // ---- mask invalid cols (last chunk only) ----
        if (rows < 64) {
#pragma unroll
            for (int j = 0; j < 2; j++) {
                const int c0 = on + j * 8 + tg * 2;
                if (c0 >= rows) {
#pragma unroll
                    for (int i = 0; i < 4; i++) { s[i][j][0] = -1e30f; s[i][j][2] = -1e30f; }
                }
                if (c0 + 1 >= rows) {
#pragma unroll
                    for (int i = 0; i < 4; i++) { s[i][j][1] = -1e30f; s[i][j][3] = -1e30f; }
                }
            }
        }

        // ---- quad-reduce row max (rows rA=om+i*16+g, rB=rA+8) ----
        float mA[4], mB[4];
#pragma unroll
        for (int i = 0; i < 4; i++) {
            mA[i] = fmaxf(fmaxf(s[i][0][0], s[i][0][1]), fmaxf(s[i][1][0], s[i][1][1]));
            mB[i] = fmaxf(fmaxf(s[i][0][2], s[i][0][3]), fmaxf(s[i][1][2], s[i][1][3]));
            mA[i] = fmaxf(mA[i], __shfl_xor_sync(~0u, mA[i], 1));
            mA[i] = fmaxf(mA[i], __shfl_xor_sync(~0u, mA[i], 2));
            mB[i] = fmaxf(mB[i], __shfl_xor_sync(~0u, mB[i], 1));
            mB[i] = fmaxf(mB[i], __shfl_xor_sync(~0u, mB[i], 2));
        }
        if (tg == 0) {
#pragma unroll
            for (int i = 0; i < 4; i++) {
                PM[wq * 128 + om + i * 16 + g]     = mA[i];
                PM[wq * 128 + om + i * 16 + g + 8] = mB[i];
            }
        }
        __syncthreads();

        // ---- combine partials, compute mnew/alpha; rescale oacc ----
        float mnA[4], mnB[4], alA[4], alB[4];
#pragma unroll
        for (int i = 0; i < 4; i++) {
            const int rA = om + i * 16 + g, rB = rA + 8;
            float ra = fmaxf(fmaxf(PM[rA], PM[128 + rA]), fmaxf(PM[256 + rA], PM[384 + rA]));
            float rb = fmaxf(fmaxf(PM[rB], PM[128 + rB]), fmaxf(PM[256 + rB], PM[384 + rB]));
            const float moA = MR[rA], moB = MR[rB];
            mnA[i] = fmaxf(moA, ra); mnB[i] = fmaxf(moB, rb);
            alA[i] = __expf(moA - mnA[i]); alB[i] = __expf(moB - mnB[i]);
#pragma unroll
            for (int j = 0; j < 2; j++) {
                oacc[i][j][0] *= alA[i]; oacc[i][j][1] *= alA[i];
                oacc[i][j][2] *= alB[i]; oacc[i][j][3] *= alB[i];
            }
        }

        // ---- exp in regs, write P (half), quad-reduce sums ----
        float sA[4], sB[4];
#pragma unroll
        for (int i = 0; i < 4; i++) {
            const int rA = om + i * 16 + g, rB = rA + 8;
            float acA = 0.f, acB = 0.f;
#pragma unroll
            for (int j = 0; j < 2; j++) {
                const int c = on + j * 8 + tg * 2;
                __half pa0 = __float2half_rn(__expf(s[i][j][0] - mnA[i]));
                __half pa1 = __float2half_rn(__expf(s[i][j][1] - mnA[i]));
                __half pb0 = __float2half_rn(__expf(s[i][j][2] - mnB[i]));
                __half pb1 = __float2half_rn(__expf(s[i][j][3] - mnB[i]));
                *(__half2*)&PH[rA * 72 + c] = __halves2half2(pa0, pa1);
                *(__half2*)&PH[rB * 72 + c] = __halves2half2(pb0, pb1);
                acA += __half2float(pa0) + __half2float(pa1);
                acB += __half2float(pb0) + __half2float(pb1);
            }
            acA += __shfl_xor_sync(~0u, acA, 1);
            acA += __shfl_xor_sync(~0u, acA, 2);
            acB += __shfl_xor_sync(~0u, acB, 1);
            acB += __shfl_xor_sync(~0u, acB, 2);
            sA[i] = acA; sB[i] = acB;
        }
        if (tg == 0) {
#pragma unroll
            for (int i = 0; i < 4; i++) {
                PL[wq * 128 + om + i * 16 + g]     = sA[i];
                PL[wq * 128 + om + i * 16 + g + 8] = sB[i];
            }
        }
        __syncthreads();

        // ---- single writer per row updates MR/LR ----
        if (wq == 0 && tg == 0) {
#pragma unroll
            for (int i = 0; i < 4; i++) {
                const int rA = om + i * 16 + g, rB = rA + 8;
                const float lsA = PL[rA] + PL[128 + rA] + PL[256 + rA] + PL[384 + rA];
                const float lsB = PL[rB] + PL[128 + rB] + PL[256 + rB] + PL[384 + rB];
                LR[rA] = LR[rA] * alA[i] + lsA;
                LR[rB] = LR[rB] * alB[i] + lsB;
                MR[rA] = mnA[i];
                MR[rB] = mnB[i];
            }
        }

        // ---- O += P @ V ----
#pragma unroll
        for (int ks = 0; ks < 4; ks++) {
            uint32_t af[4][4], bf[2][2];
#pragma unroll
            for (int i = 0; i < 4; i++) {
                const __half* base = &PH[(om + i * 16) * 72 + ks * 16];
                af[i][0] = *(const uint32_t*)&base[(g)     * 72 + 2 * tg];
                af[i][1] = *(const uint32_t*)&base[(g + 8) * 72 + 2 * tg];
                af[i][2] = *(const uint32_t*)&base[(g)     * 72 + 2 * tg + 8];
                af[i][3] = *(const uint32_t*)&base[(g + 8) * 72 + 2 * tg + 8];
            }
#pragma unroll
            for (int j = 0; j < 2; j++) {
                const __half* base = &VT[(on + j * 8 + g) * 72 + ks * 16];
                bf[j][0] = *(const uint32_t*)&base[2 * tg];
                bf[j][1] = *(const uint32_t*)&base[2 * tg + 8];
            }
#pragma unroll
            for (int i = 0; i < 4; i++)
#pragma unroll
                for (int j = 0; j < 2; j++)
                    MMA_F16(oacc[i][j][0], oacc[i][j][1], oacc[i][j][2], oacc[i][j][3],
                            af[i][0], af[i][1], af[i][2], af[i][3],
                            bf[j][0], bf[j][1]);
        }
        __syncthreads();
    }

    // ---- epilogue: O / l, rna-round for tf32 out-projection ----
    float* Ob = O + ((size_t)(b * SEQn + m0)) * 1024u + h * 64;
#pragma unroll
    for (int i = 0; i < 4; i++) {
        const int r0 = om + i * 16 + g;
        const float li0 = 1.f / LR[r0];
        const float li1 = 1.f / LR[r0 + 8];
#pragma unroll
        for (int j = 0; j < 2; j++) {
            const int c = on + j * 8 + tg * 2;
            float2 v0 = make_float2(rna_tf32(oacc[i][j][0] * li0), rna_tf32(oacc[i][j][1] * li0));
            float2 v1 = make_float2(rna_tf32(oacc[i][j][2] * li1), rna_tf32(oacc[i][j][3] * li1));
            *(float2*)&Ob[(size_t)r0 * 1024u + c]       = v0;
            *(float2*)&Ob[(size_t)(r0 + 8) * 1024u + c] = v1;
        }
    }
}

// ---------------- weight transpose (fp32 rna / fp16 rn) --------------------
__global__ void transpose_1024(const float* __restrict__ W, float* __restrict__ Wt)
{
    __shared__ float t[32][33];
    const int bx = blockIdx.x * 32, by = blockIdx.y * 32;
    const int tx = threadIdx.x, ty = threadIdx.y;
#pragma unroll
    for (int i = 0; i < 4; i++)
        t[ty + i * 8][tx] = W[(size_t)(by + ty + i * 8) * 1024 + bx + tx];
    __syncthreads();
#pragma unroll
    for (int i = 0; i < 4; i++)
        Wt[(size_t)(bx + ty + i * 8) * 1024 + by + tx] = rna_tf32(t[tx][ty + i * 8]);
}

__global__ void transpose_1024_h(const float* __restrict__ W, __half* __restrict__ Wt)
{
    __shared__ float t[32][33];
    const int bx = blockIdx.x * 32, by = blockIdx.y * 32;
    const int tx = threadIdx.x, ty = threadIdx.y;
#pragma unroll
    for (int i = 0; i < 4; i++)
        t[ty + i * 8][tx] = W[(size_t)(by + ty + i * 8) * 1024 + bx + tx];
    __syncthreads();
#pragma unroll
    for (int i = 0; i < 4; i++)
        Wt[(size_t)(bx + ty + i * 8) * 1024 + by + tx] = __float2half_rn(t[tx][ty + i * 8]);
}

// ---------------- conversion copies / trig tables ---------------------------
__global__ void half_copy(const float4* __restrict__ in, __half2* __restrict__ out, int n4)
{
    int i = blockIdx.x * blockDim.x + threadIdx.x;
    if (i < n4) {
        float4 v = in[i];
        out[2 * i]     = __floats2half2_rn(v.x, v.y);
        out[2 * i + 1] = __floats2half2_rn(v.z, v.w);
    }
}

__global__ void cs_precompute(const float* __restrict__ freqs,
                              float* __restrict__ cf, float* __restrict__ sf)
{
    int i = blockIdx.x * blockDim.x + threadIdx.x;
    if (i < 64*64*64) {
        float v = freqs[i];
        cf[i] = cosf(v);
        sf[i] = sinf(v);
    }
}

// ---------------- host launch ----------------------------------------------
extern "C" void kernel_launch(void* const* d_in, const int* in_sizes, int n_in,
                              void* d_out, int out_size)
{
    const float* x     = (const float*)d_in[0];
    const float* cond  = (const float*)d_in[1];
    const float* freqs = (const float*)d_in[2];
    const float* Wq    = (const float*)d_in[3];
    const float* Wk    = (const float*)d_in[4];
    const float* Wv    = (const float*)d_in[5];
    const float* rel   = (const float*)d_in[6];
    const float* Wo    = (const float*)d_in[7];
    const float* bo    = (const float*)d_in[8];
    const int*   memi  = (const int*)d_in[9];
    const int*   cur   = (const int*)d_in[10];
    float* out = (float*)d_out;

    float *Ob, *Wto, *Cf, *Sf;
    __half *Qh, *Kh, *Vt, *Whkv, *Whq, *Ch, *Xh;
    cudaGetSymbolAddress((void**)&Qh, g_Qh);
    cudaGetSymbolAddress((void**)&Kh, g_Kh);
    cudaGetSymbolAddress((void**)&Vt, g_Vt);
    cudaGetSymbolAddress((void**)&Ob, g_O);
    cudaGetSymbolAddress((void**)&Wto, g_Wto);
    cudaGetSymbolAddress((void**)&Whkv, g_Whkv);
    cudaGetSymbolAddress((void**)&Whq, g_Whq);
    cudaGetSymbolAddress((void**)&Ch, g_Ch);
    cudaGetSymbolAddress((void**)&Xh, g_Xh);
    cudaGetSymbolAddress((void**)&Cf, g_cosf);
    cudaGetSymbolAddress((void**)&Sf, g_sinf);

    cudaFuncSetAttribute(flash_attn, cudaFuncAttributeMaxDynamicSharedMemorySize, FL_SMEM);

    // Launch order puts gemm_kv_f16 at index 5 (ncu -s 5 -c 1 profiles it).
    half_copy<<<(ROWS_C*DIMn/4 + 255)/256, 256>>>((const float4*)cond, (__half2*)Ch, ROWS_C*DIMn/4);   // 0
    transpose_1024_h<<<dim3(32,32), dim3(32,8)>>>(Wk, Whkv);                                            // 1
    transpose_1024_h<<<dim3(32,32), dim3(32,8)>>>(Wv, Whkv + (size_t)DIMn * INNERn);                    // 2
    cs_precompute<<<(64*64*64 + 255)/256, 256>>>(freqs, Cf, Sf);                                        // 3
    half_copy<<<(ROWS_X*DIMn/4 + 255)/256, 256>>>((const float4*)x, (__half2*)Xh, ROWS_X*DIMn/4);       // 4
    // 5: merged K|V projection (PROFILED)
    gemm_kv_f16<<<dim3(16, 266), 128>>>(Ch, Whkv, Kh, Vt, Cf, Sf, rel, memi, cur, ROWS_C);
    transpose_1024_h<<<dim3(32,32), dim3(32,8)>>>(Wq, Whq);                                             // 6
    transpose_1024<<<dim3(32,32), dim3(32,8)>>>(Wo, Wto);                                               // 7
    // 8: Q projection (fp16, fused rotary+scale)
    gemm_q_f16<<<dim3(8, 32), 128>>>(Xh, Whq, Qh, Cf, Sf, cur, ROWS_X);
    // 9: fused flash attention (fp16 mma, register softmax)
    flash_attn<<<dim3(2, BHn), 256, FL_SMEM>>>(Qh, Kh, Vt, Ob);
    // 10: out = O @ Wo + bo (tf32)
    gemm_o_tf32<<<dim3(8, 32), 128>>>(Ob, Wto, out, bo, ROWS_X);
}